// round 11
// baseline (speedup 1.0000x reference)
#include <cuda_runtime.h>
#include <cstdint>

#define N_NODES 100000
#define N_EDGES 640000
#define HID     128

typedef unsigned long long ull;

// ---------------- scratch (static device globals; no allocation) ----------------
__device__ float g_A[(size_t)N_NODES * HID];   // ping
__device__ float g_B[(size_t)N_NODES * HID];   // pong
__device__ float g_S[(size_t)N_NODES * HID];   // support = X @ W
__device__ int   g_cnt[N_NODES];
__device__ int   g_rowptr[N_NODES];
__device__ int   g_cursor[N_NODES];
__device__ int   g_csr_src[N_EDGES];
__device__ float g_csr_val[N_EDGES];
__device__ int   g_blocksums[128];

// ---------------- CSR build ----------------
__global__ void hist_kernel(const int* __restrict__ dst) {
    int e = blockIdx.x * blockDim.x + threadIdx.x;
    if (e < N_EDGES) atomicAdd(&g_cnt[dst[e]], 1);
}

__global__ void scan1_kernel() {
    __shared__ int sh[1024];
    int tid = threadIdx.x;
    int i = blockIdx.x * 1024 + tid;
    int v = (i < N_NODES) ? g_cnt[i] : 0;
    sh[tid] = v;
    __syncthreads();
    for (int off = 1; off < 1024; off <<= 1) {
        int t = (tid >= off) ? sh[tid - off] : 0;
        __syncthreads();
        sh[tid] += t;
        __syncthreads();
    }
    if (i < N_NODES) g_rowptr[i] = sh[tid] - v;   // exclusive
    if (tid == 1023) g_blocksums[blockIdx.x] = sh[1023];
}

// parallel exclusive scan of the <=128 block sums
__global__ void scan2_kernel(int nblocks) {
    __shared__ int sh[128];
    int tid = threadIdx.x;
    int v = (tid < nblocks) ? g_blocksums[tid] : 0;
    sh[tid] = v;
    __syncthreads();
    for (int off = 1; off < 128; off <<= 1) {
        int t = (tid >= off) ? sh[tid - off] : 0;
        __syncthreads();
        sh[tid] += t;
        __syncthreads();
    }
    if (tid < nblocks) g_blocksums[tid] = sh[tid] - v;   // exclusive
}

__global__ void scan3_kernel() {
    int i = blockIdx.x * 1024 + threadIdx.x;
    if (i < N_NODES) {
        int r = g_rowptr[i] + g_blocksums[blockIdx.x];
        g_rowptr[i] = r;
        g_cursor[i] = r;
    }
}

__global__ void scatter_kernel(const int* __restrict__ src,
                               const int* __restrict__ dst,
                               const float* __restrict__ val) {
    int e = blockIdx.x * blockDim.x + threadIdx.x;
    if (e < N_EDGES) {
        int d = dst[e];
        int pos = atomicAdd(&g_cursor[d], 1);
        g_csr_src[pos] = src[e];
        g_csr_val[pos] = val[e];
    }
}

// ---------------- embedding concat ----------------
__global__ void embed_kernel(const int* __restrict__ nodef,
                             const int* __restrict__ typef,
                             const int* __restrict__ lenf,
                             const int* __restrict__ lanef,
                             const float* __restrict__ node_emb,
                             const float* __restrict__ type_emb,
                             const float* __restrict__ len_emb,
                             const float* __restrict__ lane_emb) {
    int u = blockIdx.x * blockDim.x + threadIdx.x;
    if (u >= N_NODES * 32) return;
    int n = u >> 5;
    int c = u & 31;
    float4 v;
    if (c < 4) {
        int f = lanef[n];
        v = reinterpret_cast<const float4*>(lane_emb + (size_t)f * 16)[c];
    } else if (c < 12) {
        int f = typef[n];
        v = reinterpret_cast<const float4*>(type_emb + (size_t)f * 32)[c - 4];
    } else if (c < 16) {
        int f = lenf[n];
        v = reinterpret_cast<const float4*>(len_emb + (size_t)f * 16)[c - 12];
    } else {
        int f = nodef[n];
        v = reinterpret_cast<const float4*>(node_emb + (size_t)f * 64)[c - 16];
    }
    reinterpret_cast<float4*>(g_A)[u] = v;
}

// ---------------- GEMM via packed f32x2 FFMA2 + duplicated-X smem ----------------
// S[r][c] = sum_k X[r][k] * W[k][c].  Tile: 32 rows x 128 cols (100000 = 3125*32).
// 256 threads: thread (ty=tid>>4 -> row pair 2ty,2ty+1; tx=tid&15 -> col pairs
// (2tx+32j, 2tx+32j+1), j<4).  X stored in smem as {x,x} 8B pairs so the inner
// loop broadcast is ONE LDS.64 (no mov.b64 packing).  W (64KB) loaded once per
// persistent CTA.  Inner loop per thread-k: 4 LDS.64 (W) + 2 LDS.64 (Xdup) +
// 8 FFMA2 = 14 issue slots vs 16 fma-pipe cycles -> fma-bound.
#define XD_STRIDE 129                           // ull per row (pad: 1032B pitch)
#define GEMM_TILES (N_NODES / 32)               // 3125 exact
#define SMEM_GEMM (128 * 128 * 4 + 32 * XD_STRIDE * 8)   // 65536+33024=98560

__device__ __forceinline__ void ffma2(ull& acc, ull a, ull b) {
    asm("fma.rn.f32x2 %0, %1, %2, %0;" : "+l"(acc) : "l"(a), "l"(b));
}
__device__ __forceinline__ ull pack2(float v) {
    ull r;
    asm("mov.b64 %0, {%1, %1};" : "=l"(r) : "f"(v));
    return r;
}

__global__ __launch_bounds__(256, 2)
void gemm_kernel(const float* __restrict__ X,
                 const float* __restrict__ W,
                 float* __restrict__ S) {
    extern __shared__ float sh[];
    float* ws = sh;                                        // 128*128 floats
    ull*   xd = reinterpret_cast<ull*>(sh + 128 * 128);    // 32 * XD_STRIDE ull
    int tid = threadIdx.x;

    // load W once (coalesced float4)
    for (int i = tid; i < 128 * 128 / 4; i += 256)
        reinterpret_cast<float4*>(ws)[i] = reinterpret_cast<const float4*>(W)[i];

    int tx = tid & 15;
    int ty = tid >> 4;
    const float* wcol = ws + 2 * tx;
    const ull* xrow0 = xd + (2 * ty) * XD_STRIDE;
    const ull* xrow1 = xd + (2 * ty + 1) * XD_STRIDE;

    for (int tile = blockIdx.x; tile < GEMM_TILES; tile += gridDim.x) {
        int row0 = tile * 32;
        __syncthreads();   // previous compute done reading xd (also orders W on iter 0)
        // fill X tile duplicated: 32 rows x 32 float4 -> 4 iters/thread
        for (int i = tid; i < 32 * 32; i += 256) {
            int r = i >> 5, c4 = i & 31;
            float4 v = reinterpret_cast<const float4*>(X + (size_t)(row0 + r) * 128)[c4];
            ull* dst = xd + r * XD_STRIDE + 4 * c4;
            dst[0] = pack2(v.x); dst[1] = pack2(v.y);
            dst[2] = pack2(v.z); dst[3] = pack2(v.w);
        }
        __syncthreads();

        ull acc[2][4];
#pragma unroll
        for (int i = 0; i < 2; i++)
#pragma unroll
            for (int j = 0; j < 4; j++) acc[i][j] = 0ull;

#pragma unroll 16
        for (int k = 0; k < 128; k++) {
            ull x0 = xrow0[k];
            ull x1 = xrow1[k];
#pragma unroll
            for (int j = 0; j < 4; j++) {
                ull wv = *reinterpret_cast<const ull*>(wcol + k * 128 + 32 * j);
                ffma2(acc[0][j], x0, wv);
                ffma2(acc[1][j], x1, wv);
            }
        }

        // epilogue: float2 stores, coalesced
#pragma unroll
        for (int i = 0; i < 2; i++) {
            int gr = row0 + 2 * ty + i;
            float* out = S + (size_t)gr * 128 + 2 * tx;
#pragma unroll
            for (int j = 0; j < 4; j++)
                *reinterpret_cast<float2*>(out + 32 * j) =
                    *reinterpret_cast<float2*>(&acc[i][j]);
        }
    }
}

// ---------------- aggregation: out[d] = b + sum_{e: dst=d} val_e * S[src_e] ----------------
__global__ void agg_kernel(const float* __restrict__ S,
                           const float* __restrict__ b,
                           float* __restrict__ out) {
    int warp = (blockIdx.x * blockDim.x + threadIdx.x) >> 5;
    int lane = threadIdx.x & 31;
    if (warp >= N_NODES) return;
    float4 acc = reinterpret_cast<const float4*>(b)[lane];
    int s = g_rowptr[warp];
    int e = g_cursor[warp];
    for (int j = s; j < e; j++) {
        int src = __ldg(&g_csr_src[j]);
        float v = __ldg(&g_csr_val[j]);
        float4 x = reinterpret_cast<const float4*>(S + (size_t)src * 128)[lane];
        acc.x = fmaf(v, x.x, acc.x);
        acc.y = fmaf(v, x.y, acc.y);
        acc.z = fmaf(v, x.z, acc.z);
        acc.w = fmaf(v, x.w, acc.w);
    }
    reinterpret_cast<float4*>(out + (size_t)warp * 128)[lane] = acc;
}

// ---------------- launch ----------------
extern "C" void kernel_launch(void* const* d_in, const int* in_sizes, int n_in,
                              void* d_out, int out_size) {
    const int*   nodef    = (const int*)d_in[0];
    const int*   typef    = (const int*)d_in[1];
    const int*   lenf     = (const int*)d_in[2];
    const int*   lanef    = (const int*)d_in[3];
    const int*   adj_src  = (const int*)d_in[4];
    const int*   adj_dst  = (const int*)d_in[5];
    const float* adj_val  = (const float*)d_in[6];
    const float* node_emb = (const float*)d_in[7];
    const float* type_emb = (const float*)d_in[8];
    const float* len_emb  = (const float*)d_in[9];
    const float* lane_emb = (const float*)d_in[10];
    const float* W        = (const float*)d_in[11];
    const float* b        = (const float*)d_in[12];
    float* out = (float*)d_out;

    float *pA, *pB, *pS;
    int* pcnt;
    cudaGetSymbolAddress((void**)&pA, g_A);
    cudaGetSymbolAddress((void**)&pB, g_B);
    cudaGetSymbolAddress((void**)&pS, g_S);
    cudaGetSymbolAddress((void**)&pcnt, g_cnt);

    cudaFuncSetAttribute(gemm_kernel, cudaFuncAttributeMaxDynamicSharedMemorySize, SMEM_GEMM);

    const int gemm_blocks = 2 * 148;                    // persistent, 2 CTAs/SM
    const int agg_blocks  = (N_NODES * 32 + 255) / 256;
    const int nscan = (N_NODES + 1023) / 1024;          // 98

    // Launch order puts gemm_kernel at launch index 4 (ncu captures idx 4):
    // memset(0), embed(1), hist(2), scan1(3), gemm1(4), scan2, scan3, scatter, ...
    cudaMemsetAsync(pcnt, 0, N_NODES * sizeof(int));                           // 0
    embed_kernel<<<(N_NODES * 32 + 255) / 256, 256>>>(nodef, typef, lenf, lanef,
                                                      node_emb, type_emb, len_emb, lane_emb); // 1
    hist_kernel<<<(N_EDGES + 255) / 256, 256>>>(adj_dst);                      // 2
    scan1_kernel<<<nscan, 1024>>>();                                           // 3
    gemm_kernel<<<gemm_blocks, 256, SMEM_GEMM>>>(pA, W, pS);                   // 4 (profiled)
    scan2_kernel<<<1, 128>>>(nscan);                                           // 5
    scan3_kernel<<<nscan, 1024>>>();                                           // 6
    scatter_kernel<<<(N_EDGES + 255) / 256, 256>>>(adj_src, adj_dst, adj_val); // 7

    agg_kernel<<<agg_blocks, 256>>>(pS, b, pB);
    gemm_kernel<<<gemm_blocks, 256, SMEM_GEMM>>>(pB, W, pS);
    agg_kernel<<<agg_blocks, 256>>>(pS, b, pA);
    gemm_kernel<<<gemm_blocks, 256, SMEM_GEMM>>>(pA, W, pS);
    agg_kernel<<<agg_blocks, 256>>>(pS, b, out);
}

// round 13
// speedup vs baseline: 1.3209x; 1.3209x over previous
#include <cuda_runtime.h>
#include <cstdint>

#define N_NODES 100000
#define N_EDGES 640000
#define HID     128

typedef unsigned long long ull;

// ---------------- scratch (static device globals; no allocation) ----------------
__device__ float g_A[(size_t)N_NODES * HID];   // ping
__device__ float g_B[(size_t)N_NODES * HID];   // pong
__device__ float g_S[(size_t)N_NODES * HID];   // support = X @ W
__device__ int   g_cnt[N_NODES];
__device__ int   g_rowptr[N_NODES];
__device__ int   g_cursor[N_NODES];
__device__ int   g_csr_src[N_EDGES];
__device__ float g_csr_val[N_EDGES];
__device__ int   g_blocksums[128];

// ---------------- CSR build ----------------
__global__ void hist_kernel(const int* __restrict__ dst) {
    int e = blockIdx.x * blockDim.x + threadIdx.x;
    if (e < N_EDGES) atomicAdd(&g_cnt[dst[e]], 1);
}

__global__ void scan1_kernel() {
    __shared__ int sh[1024];
    int tid = threadIdx.x;
    int i = blockIdx.x * 1024 + tid;
    int v = (i < N_NODES) ? g_cnt[i] : 0;
    sh[tid] = v;
    __syncthreads();
    for (int off = 1; off < 1024; off <<= 1) {
        int t = (tid >= off) ? sh[tid - off] : 0;
        __syncthreads();
        sh[tid] += t;
        __syncthreads();
    }
    if (i < N_NODES) g_rowptr[i] = sh[tid] - v;   // exclusive
    if (tid == 1023) g_blocksums[blockIdx.x] = sh[1023];
}

// parallel exclusive scan of the <=128 block sums
__global__ void scan2_kernel(int nblocks) {
    __shared__ int sh[128];
    int tid = threadIdx.x;
    int v = (tid < nblocks) ? g_blocksums[tid] : 0;
    sh[tid] = v;
    __syncthreads();
    for (int off = 1; off < 128; off <<= 1) {
        int t = (tid >= off) ? sh[tid - off] : 0;
        __syncthreads();
        sh[tid] += t;
        __syncthreads();
    }
    if (tid < nblocks) g_blocksums[tid] = sh[tid] - v;   // exclusive
}

__global__ void scan3_kernel() {
    int i = blockIdx.x * 1024 + threadIdx.x;
    if (i < N_NODES) {
        int r = g_rowptr[i] + g_blocksums[blockIdx.x];
        g_rowptr[i] = r;
        g_cursor[i] = r;
    }
}

__global__ void scatter_kernel(const int* __restrict__ src,
                               const int* __restrict__ dst,
                               const float* __restrict__ val) {
    int e = blockIdx.x * blockDim.x + threadIdx.x;
    if (e < N_EDGES) {
        int d = dst[e];
        int pos = atomicAdd(&g_cursor[d], 1);
        g_csr_src[pos] = src[e];
        g_csr_val[pos] = val[e];
    }
}

// ---------------- embedding concat ----------------
__global__ void embed_kernel(const int* __restrict__ nodef,
                             const int* __restrict__ typef,
                             const int* __restrict__ lenf,
                             const int* __restrict__ lanef,
                             const float* __restrict__ node_emb,
                             const float* __restrict__ type_emb,
                             const float* __restrict__ len_emb,
                             const float* __restrict__ lane_emb) {
    int u = blockIdx.x * blockDim.x + threadIdx.x;
    if (u >= N_NODES * 32) return;
    int n = u >> 5;
    int c = u & 31;
    float4 v;
    if (c < 4) {
        int f = lanef[n];
        v = reinterpret_cast<const float4*>(lane_emb + (size_t)f * 16)[c];
    } else if (c < 12) {
        int f = typef[n];
        v = reinterpret_cast<const float4*>(type_emb + (size_t)f * 32)[c - 4];
    } else if (c < 16) {
        int f = lenf[n];
        v = reinterpret_cast<const float4*>(len_emb + (size_t)f * 16)[c - 12];
    } else {
        int f = nodef[n];
        v = reinterpret_cast<const float4*>(node_emb + (size_t)f * 64)[c - 16];
    }
    reinterpret_cast<float4*>(g_A)[u] = v;
}

// ---------------- GEMM: FFMA2 with k-pair accumulation, col-split W ----------------
// S[r][c] = sum_k X[r][k] * W[k][c].
// Grid 296 persistent CTAs: CTA < 148 handles cols [0,64), else [64,128);
// each loops over 782 row-tiles of 128 rows.  256 threads.
// W half pre-packed per CTA as Wp[k2][c] = {W[2k2][c], W[2k2+1][c]}  (32 KB).
// X tile natural layout (128 x 128, stride 132 floats, 67.6 KB) -> ~100 KB, 2 CTAs/SM.
// Thread (ty=tid>>4, tx=tid&15): rows ty+16i (i<8), cols tx+16j (j<4)  [full 64-col half].
// Per k2: x = natural LDS.64 pair {X[r][2k2],X[r][2k2+1]} (no packing movs);
// FFMA2 lanes hold even-k / odd-k partial sums; final = lo + hi.
#define XN_STRIDE 132
#define ROW_TILES ((N_NODES + 127) / 128)     // 782
#define SMEM_GEMM (64 * 64 * 8 + 128 * XN_STRIDE * 4)   // 32768+67584=100352

__device__ __forceinline__ void ffma2(ull& acc, ull a, ull b) {
    asm("fma.rn.f32x2 %0, %1, %2, %0;" : "+l"(acc) : "l"(a), "l"(b));
}

__global__ __launch_bounds__(256, 2)
void gemm_kernel(const float* __restrict__ X,
                 const float* __restrict__ W,
                 float* __restrict__ S) {
    extern __shared__ float sh[];
    ull*   wp = reinterpret_cast<ull*>(sh);          // [64 k2][64 c]
    float* xs = sh + 64 * 64 * 2;                    // 128 x XN_STRIDE
    int tid = threadIdx.x;
    int half  = (blockIdx.x >= 148) ? 1 : 0;
    int cbase = half * 64;

    // pack W half once per CTA: Wp[k2][c] = {W[2k2][cbase+c], W[2k2+1][cbase+c]}
    for (int i = tid; i < 64 * 64; i += 256) {
        int k2 = i >> 6, c = i & 63;
        float w0 = W[(2 * k2) * 128 + cbase + c];
        float w1 = W[(2 * k2 + 1) * 128 + cbase + c];
        ull v;
        asm("mov.b64 %0, {%1, %2};" : "=l"(v) : "f"(w0), "f"(w1));
        wp[i] = v;
    }

    int tx = tid & 15;
    int ty = tid >> 4;

    for (int tile = blockIdx.x % 148; tile < ROW_TILES; tile += 148) {
        int row0 = tile * 128;
        __syncthreads();   // previous iter's readers done with xs (W ready iter 0)
        // fill X tile (natural float4, aligned: 132*4=528 = 33*16)
        for (int i = tid; i < 128 * 32; i += 256) {
            int r = i >> 5, c4 = i & 31;
            int gr = row0 + r;
            float4 v = make_float4(0.f, 0.f, 0.f, 0.f);
            if (gr < N_NODES)
                v = reinterpret_cast<const float4*>(X + (size_t)gr * 128)[c4];
            *reinterpret_cast<float4*>(xs + r * XN_STRIDE + 4 * c4) = v;
        }
        __syncthreads();

        ull acc[8][4];
#pragma unroll
        for (int i = 0; i < 8; i++)
#pragma unroll
            for (int j = 0; j < 4; j++) acc[i][j] = 0ull;

#pragma unroll 4
        for (int k2 = 0; k2 < 64; k2++) {
            ull w[4];
#pragma unroll
            for (int j = 0; j < 4; j++) w[j] = wp[k2 * 64 + tx + 16 * j];
            ull x[8];
#pragma unroll
            for (int i = 0; i < 8; i++)
                x[i] = *reinterpret_cast<const ull*>(xs + (ty + 16 * i) * XN_STRIDE + 2 * k2);
#pragma unroll
            for (int i = 0; i < 8; i++)
#pragma unroll
                for (int j = 0; j < 4; j++)
                    ffma2(acc[i][j], x[i], w[j]);
        }

        // epilogue: combine even/odd partial sums, store (full 64-col half)
#pragma unroll
        for (int i = 0; i < 8; i++) {
            int gr = row0 + ty + 16 * i;
            if (gr < N_NODES) {
                float* out = S + (size_t)gr * 128 + cbase + tx;
#pragma unroll
                for (int j = 0; j < 4; j++) {
                    float2 a = *reinterpret_cast<float2*>(&acc[i][j]);
                    out[16 * j] = a.x + a.y;
                }
            }
        }
    }
}

// ---------------- aggregation: out[d] = b + sum_{e: dst=d} val_e * S[src_e] ----------------
__global__ void agg_kernel(const float* __restrict__ S,
                           const float* __restrict__ b,
                           float* __restrict__ out) {
    int warp = (blockIdx.x * blockDim.x + threadIdx.x) >> 5;
    int lane = threadIdx.x & 31;
    if (warp >= N_NODES) return;
    float4 acc = reinterpret_cast<const float4*>(b)[lane];
    int s = g_rowptr[warp];
    int e = g_cursor[warp];
    for (int j = s; j < e; j++) {
        int src = __ldg(&g_csr_src[j]);
        float v = __ldg(&g_csr_val[j]);
        float4 x = reinterpret_cast<const float4*>(S + (size_t)src * 128)[lane];
        acc.x = fmaf(v, x.x, acc.x);
        acc.y = fmaf(v, x.y, acc.y);
        acc.z = fmaf(v, x.z, acc.z);
        acc.w = fmaf(v, x.w, acc.w);
    }
    reinterpret_cast<float4*>(out + (size_t)warp * 128)[lane] = acc;
}

// ---------------- launch ----------------
extern "C" void kernel_launch(void* const* d_in, const int* in_sizes, int n_in,
                              void* d_out, int out_size) {
    const int*   nodef    = (const int*)d_in[0];
    const int*   typef    = (const int*)d_in[1];
    const int*   lenf     = (const int*)d_in[2];
    const int*   lanef    = (const int*)d_in[3];
    const int*   adj_src  = (const int*)d_in[4];
    const int*   adj_dst  = (const int*)d_in[5];
    const float* adj_val  = (const float*)d_in[6];
    const float* node_emb = (const float*)d_in[7];
    const float* type_emb = (const float*)d_in[8];
    const float* len_emb  = (const float*)d_in[9];
    const float* lane_emb = (const float*)d_in[10];
    const float* W        = (const float*)d_in[11];
    const float* b        = (const float*)d_in[12];
    float* out = (float*)d_out;

    float *pA, *pB, *pS;
    int* pcnt;
    cudaGetSymbolAddress((void**)&pA, g_A);
    cudaGetSymbolAddress((void**)&pB, g_B);
    cudaGetSymbolAddress((void**)&pS, g_S);
    cudaGetSymbolAddress((void**)&pcnt, g_cnt);

    cudaFuncSetAttribute(gemm_kernel, cudaFuncAttributeMaxDynamicSharedMemorySize, SMEM_GEMM);

    const int gemm_blocks = 2 * 148;                    // persistent; col-half per 148
    const int agg_blocks  = (N_NODES * 32 + 255) / 256;
    const int nscan = (N_NODES + 1023) / 1024;          // 98

    // Launch order keeps gemm_kernel at launch index 4 (ncu captures idx 4):
    cudaMemsetAsync(pcnt, 0, N_NODES * sizeof(int));                           // 0
    embed_kernel<<<(N_NODES * 32 + 255) / 256, 256>>>(nodef, typef, lenf, lanef,
                                                      node_emb, type_emb, len_emb, lane_emb); // 1
    hist_kernel<<<(N_EDGES + 255) / 256, 256>>>(adj_dst);                      // 2
    scan1_kernel<<<nscan, 1024>>>();                                           // 3
    gemm_kernel<<<gemm_blocks, 256, SMEM_GEMM>>>(pA, W, pS);                   // 4 (profiled)
    scan2_kernel<<<1, 128>>>(nscan);                                           // 5
    scan3_kernel<<<nscan, 1024>>>();                                           // 6
    scatter_kernel<<<(N_EDGES + 255) / 256, 256>>>(adj_src, adj_dst, adj_val); // 7

    agg_kernel<<<agg_blocks, 256>>>(pS, b, pB);
    gemm_kernel<<<gemm_blocks, 256, SMEM_GEMM>>>(pB, W, pS);
    agg_kernel<<<agg_blocks, 256>>>(pS, b, pA);
    gemm_kernel<<<gemm_blocks, 256, SMEM_GEMM>>>(pA, W, pS);
    agg_kernel<<<agg_blocks, 256>>>(pS, b, out);
}

// round 14
// speedup vs baseline: 1.3697x; 1.0369x over previous
#include <cuda_runtime.h>
#include <cstdint>

#define N_NODES 100000
#define N_EDGES 640000
#define HID     128

typedef unsigned long long ull;

// ---------------- scratch (static device globals; no allocation) ----------------
__device__ float g_A[(size_t)N_NODES * HID];   // ping
__device__ float g_B[(size_t)N_NODES * HID];   // pong
__device__ float g_S[(size_t)N_NODES * HID];   // support = X @ W
__device__ int   g_cnt[N_NODES];
__device__ int   g_rowptr[N_NODES];
__device__ int   g_cursor[N_NODES];
__device__ int   g_csr_src[N_EDGES];
__device__ float g_csr_val[N_EDGES];
__device__ int   g_blocksums[128];

// ---------------- CSR build ----------------
__global__ void hist_kernel(const int* __restrict__ dst) {
    int e = blockIdx.x * blockDim.x + threadIdx.x;
    if (e < N_EDGES) atomicAdd(&g_cnt[dst[e]], 1);
}

__global__ void scan1_kernel() {
    __shared__ int sh[1024];
    int tid = threadIdx.x;
    int i = blockIdx.x * 1024 + tid;
    int v = (i < N_NODES) ? g_cnt[i] : 0;
    sh[tid] = v;
    __syncthreads();
    for (int off = 1; off < 1024; off <<= 1) {
        int t = (tid >= off) ? sh[tid - off] : 0;
        __syncthreads();
        sh[tid] += t;
        __syncthreads();
    }
    if (i < N_NODES) g_rowptr[i] = sh[tid] - v;   // exclusive
    if (tid == 1023) g_blocksums[blockIdx.x] = sh[1023];
}

// parallel exclusive scan of the <=128 block sums
__global__ void scan2_kernel(int nblocks) {
    __shared__ int sh[128];
    int tid = threadIdx.x;
    int v = (tid < nblocks) ? g_blocksums[tid] : 0;
    sh[tid] = v;
    __syncthreads();
    for (int off = 1; off < 128; off <<= 1) {
        int t = (tid >= off) ? sh[tid - off] : 0;
        __syncthreads();
        sh[tid] += t;
        __syncthreads();
    }
    if (tid < nblocks) g_blocksums[tid] = sh[tid] - v;   // exclusive
}

__global__ void scan3_kernel() {
    int i = blockIdx.x * 1024 + threadIdx.x;
    if (i < N_NODES) {
        int r = g_rowptr[i] + g_blocksums[blockIdx.x];
        g_rowptr[i] = r;
        g_cursor[i] = r;
    }
}

__global__ void scatter_kernel(const int* __restrict__ src,
                               const int* __restrict__ dst,
                               const float* __restrict__ val) {
    int e = blockIdx.x * blockDim.x + threadIdx.x;
    if (e < N_EDGES) {
        int d = dst[e];
        int pos = atomicAdd(&g_cursor[d], 1);
        g_csr_src[pos] = src[e];
        g_csr_val[pos] = val[e];
    }
}

// ---------------- embedding concat ----------------
__global__ void embed_kernel(const int* __restrict__ nodef,
                             const int* __restrict__ typef,
                             const int* __restrict__ lenf,
                             const int* __restrict__ lanef,
                             const float* __restrict__ node_emb,
                             const float* __restrict__ type_emb,
                             const float* __restrict__ len_emb,
                             const float* __restrict__ lane_emb) {
    int u = blockIdx.x * blockDim.x + threadIdx.x;
    if (u >= N_NODES * 32) return;
    int n = u >> 5;
    int c = u & 31;
    float4 v;
    if (c < 4) {
        int f = lanef[n];
        v = reinterpret_cast<const float4*>(lane_emb + (size_t)f * 16)[c];
    } else if (c < 12) {
        int f = typef[n];
        v = reinterpret_cast<const float4*>(type_emb + (size_t)f * 32)[c - 4];
    } else if (c < 16) {
        int f = lenf[n];
        v = reinterpret_cast<const float4*>(len_emb + (size_t)f * 16)[c - 12];
    } else {
        int f = nodef[n];
        v = reinterpret_cast<const float4*>(node_emb + (size_t)f * 64)[c - 16];
    }
    reinterpret_cast<float4*>(g_A)[u] = v;
}

// ---------------- GEMM: FFMA2 k-pair accumulation, col-split W, 3 CTAs/SM ----------------
// S[r][c] = sum_k X[r][k] * W[k][c].
// Grid 444 persistent CTAs: CTA < 222 -> cols [0,64), else [64,128);
// each strides over 1563 row-tiles of 64 rows.  256 threads.
// W half pre-packed per CTA as Wp[k2][c] = {W[2k2][c], W[2k2+1][c]}  (32 KB).
// X tile natural layout (64 x 128, stride 132 floats, 33.8 KB) -> 65 KB -> 3 CTAs/SM.
// Thread (ty=tid>>4, tx=tid&15): rows ty+16i (i<4), cols tx+16j (j<4).
// acc[4][4] = 32 regs -> total ~70 regs: room for ptxas pipelining (R13 was reg-capped at 128).
#define XN_STRIDE 132
#define ROW_TILES64 ((N_NODES + 63) / 64)     // 1563
#define HALF_CTAS 222
#define SMEM_GEMM (64 * 64 * 8 + 64 * XN_STRIDE * 4)   // 32768+33792=66560

__device__ __forceinline__ void ffma2(ull& acc, ull a, ull b) {
    asm("fma.rn.f32x2 %0, %1, %2, %0;" : "+l"(acc) : "l"(a), "l"(b));
}

__global__ __launch_bounds__(256, 3)
void gemm_kernel(const float* __restrict__ X,
                 const float* __restrict__ W,
                 float* __restrict__ S) {
    extern __shared__ float sh[];
    ull*   wp = reinterpret_cast<ull*>(sh);          // [64 k2][64 c]
    float* xs = sh + 64 * 64 * 2;                    // 64 x XN_STRIDE
    int tid = threadIdx.x;
    int half  = (blockIdx.x >= HALF_CTAS) ? 1 : 0;
    int cbase = half * 64;

    // pack W half once per CTA: Wp[k2][c] = {W[2k2][cbase+c], W[2k2+1][cbase+c]}
    for (int i = tid; i < 64 * 64; i += 256) {
        int k2 = i >> 6, c = i & 63;
        float w0 = W[(2 * k2) * 128 + cbase + c];
        float w1 = W[(2 * k2 + 1) * 128 + cbase + c];
        ull v;
        asm("mov.b64 %0, {%1, %2};" : "=l"(v) : "f"(w0), "f"(w1));
        wp[i] = v;
    }

    int tx = tid & 15;
    int ty = tid >> 4;

    for (int tile = blockIdx.x % HALF_CTAS; tile < ROW_TILES64; tile += HALF_CTAS) {
        int row0 = tile * 64;
        __syncthreads();   // previous iter's readers done with xs (W ready iter 0)
        // fill X tile (natural float4, aligned: 132*4=528 = 33*16)
        for (int i = tid; i < 64 * 32; i += 256) {
            int r = i >> 5, c4 = i & 31;
            int gr = row0 + r;
            float4 v = make_float4(0.f, 0.f, 0.f, 0.f);
            if (gr < N_NODES)
                v = reinterpret_cast<const float4*>(X + (size_t)gr * 128)[c4];
            *reinterpret_cast<float4*>(xs + r * XN_STRIDE + 4 * c4) = v;
        }
        __syncthreads();

        ull acc[4][4];
#pragma unroll
        for (int i = 0; i < 4; i++)
#pragma unroll
            for (int j = 0; j < 4; j++) acc[i][j] = 0ull;

#pragma unroll 8
        for (int k2 = 0; k2 < 64; k2++) {
            ull w[4];
#pragma unroll
            for (int j = 0; j < 4; j++) w[j] = wp[k2 * 64 + tx + 16 * j];
            ull x[4];
#pragma unroll
            for (int i = 0; i < 4; i++)
                x[i] = *reinterpret_cast<const ull*>(xs + (ty + 16 * i) * XN_STRIDE + 2 * k2);
#pragma unroll
            for (int i = 0; i < 4; i++)
#pragma unroll
                for (int j = 0; j < 4; j++)
                    ffma2(acc[i][j], x[i], w[j]);
        }

        // epilogue: combine even/odd partial sums, store
#pragma unroll
        for (int i = 0; i < 4; i++) {
            int gr = row0 + ty + 16 * i;
            if (gr < N_NODES) {
                float* out = S + (size_t)gr * 128 + cbase + tx;
#pragma unroll
                for (int j = 0; j < 4; j++) {
                    float2 a = *reinterpret_cast<float2*>(&acc[i][j]);
                    out[16 * j] = a.x + a.y;
                }
            }
        }
    }
}

// ---------------- aggregation: out[d] = b + sum_{e: dst=d} val_e * S[src_e] ----------------
__global__ void agg_kernel(const float* __restrict__ S,
                           const float* __restrict__ b,
                           float* __restrict__ out) {
    int warp = (blockIdx.x * blockDim.x + threadIdx.x) >> 5;
    int lane = threadIdx.x & 31;
    if (warp >= N_NODES) return;
    float4 acc = reinterpret_cast<const float4*>(b)[lane];
    int s = g_rowptr[warp];
    int e = g_cursor[warp];
    for (int j = s; j < e; j++) {
        int src = __ldg(&g_csr_src[j]);
        float v = __ldg(&g_csr_val[j]);
        float4 x = reinterpret_cast<const float4*>(S + (size_t)src * 128)[lane];
        acc.x = fmaf(v, x.x, acc.x);
        acc.y = fmaf(v, x.y, acc.y);
        acc.z = fmaf(v, x.z, acc.z);
        acc.w = fmaf(v, x.w, acc.w);
    }
    reinterpret_cast<float4*>(out + (size_t)warp * 128)[lane] = acc;
}

// ---------------- launch ----------------
extern "C" void kernel_launch(void* const* d_in, const int* in_sizes, int n_in,
                              void* d_out, int out_size) {
    const int*   nodef    = (const int*)d_in[0];
    const int*   typef    = (const int*)d_in[1];
    const int*   lenf     = (const int*)d_in[2];
    const int*   lanef    = (const int*)d_in[3];
    const int*   adj_src  = (const int*)d_in[4];
    const int*   adj_dst  = (const int*)d_in[5];
    const float* adj_val  = (const float*)d_in[6];
    const float* node_emb = (const float*)d_in[7];
    const float* type_emb = (const float*)d_in[8];
    const float* len_emb  = (const float*)d_in[9];
    const float* lane_emb = (const float*)d_in[10];
    const float* W        = (const float*)d_in[11];
    const float* b        = (const float*)d_in[12];
    float* out = (float*)d_out;

    float *pA, *pB, *pS;
    int* pcnt;
    cudaGetSymbolAddress((void**)&pA, g_A);
    cudaGetSymbolAddress((void**)&pB, g_B);
    cudaGetSymbolAddress((void**)&pS, g_S);
    cudaGetSymbolAddress((void**)&pcnt, g_cnt);

    cudaFuncSetAttribute(gemm_kernel, cudaFuncAttributeMaxDynamicSharedMemorySize, SMEM_GEMM);

    const int gemm_blocks = 2 * HALF_CTAS;              // 444 persistent, 3 CTAs/SM
    const int agg_blocks  = (N_NODES * 32 + 255) / 256;
    const int nscan = (N_NODES + 1023) / 1024;          // 98

    // Launch order keeps gemm_kernel at launch index 4 (ncu captures idx 4):
    cudaMemsetAsync(pcnt, 0, N_NODES * sizeof(int));                           // 0
    embed_kernel<<<(N_NODES * 32 + 255) / 256, 256>>>(nodef, typef, lenf, lanef,
                                                      node_emb, type_emb, len_emb, lane_emb); // 1
    hist_kernel<<<(N_EDGES + 255) / 256, 256>>>(adj_dst);                      // 2
    scan1_kernel<<<nscan, 1024>>>();                                           // 3
    gemm_kernel<<<gemm_blocks, 256, SMEM_GEMM>>>(pA, W, pS);                   // 4 (profiled)
    scan2_kernel<<<1, 128>>>(nscan);                                           // 5
    scan3_kernel<<<nscan, 1024>>>();                                           // 6
    scatter_kernel<<<(N_EDGES + 255) / 256, 256>>>(adj_src, adj_dst, adj_val); // 7

    agg_kernel<<<agg_blocks, 256>>>(pS, b, pB);
    gemm_kernel<<<gemm_blocks, 256, SMEM_GEMM>>>(pB, W, pS);
    agg_kernel<<<agg_blocks, 256>>>(pS, b, pA);
    gemm_kernel<<<gemm_blocks, 256, SMEM_GEMM>>>(pA, W, pS);
    agg_kernel<<<agg_blocks, 256>>>(pS, b, out);
}

// round 15
// speedup vs baseline: 1.7396x; 1.2701x over previous
#include <cuda_runtime.h>
#include <cstdint>

#define N_NODES 100000
#define N_EDGES 640000
#define HID     128

typedef unsigned long long ull;

// ---------------- scratch (static device globals; no allocation) ----------------
__device__ float  g_A[(size_t)N_NODES * HID];   // embed out / T2
__device__ float  g_B[(size_t)N_NODES * HID];   // T1
__device__ float  g_S[(size_t)N_NODES * HID];   // Y = X * W^3
__device__ int    g_cnt[N_NODES];
__device__ int    g_rowptr[N_NODES];
__device__ int    g_cursor[N_NODES];
__device__ int    g_csr_src[N_EDGES];
__device__ float  g_csr_val[N_EDGES];
__device__ int    g_blocksums[128];
__device__ double g_W2d[128 * 128];             // W^2 in fp64
__device__ float  g_W3[128 * 128];              // W^3 fp32 (GEMM operand)
__device__ float  g_c1[HID];                    // b^T W
__device__ float  g_c2[HID];                    // b^T W^2
__device__ float  g_deg1[N_NODES];              // A·1
__device__ float  g_deg2[N_NODES];              // A²·1

// ---------------- small matrix prep (fp64 accumulation) ----------------
__global__ void w2_kernel(const float* __restrict__ W) {
    int i = blockIdx.x * blockDim.x + threadIdx.x;   // 16384
    int r = i >> 7, c = i & 127;
    double acc = 0.0;
    for (int k = 0; k < 128; k++)
        acc += (double)W[r * 128 + k] * (double)W[k * 128 + c];
    g_W2d[i] = acc;
}

__global__ void w3_kernel(const float* __restrict__ W) {
    int i = blockIdx.x * blockDim.x + threadIdx.x;
    int r = i >> 7, c = i & 127;
    double acc = 0.0;
    for (int k = 0; k < 128; k++)
        acc += g_W2d[r * 128 + k] * (double)W[k * 128 + c];
    g_W3[i] = (float)acc;
}

__global__ void c12_kernel(const float* __restrict__ W, const float* __restrict__ b) {
    int j = threadIdx.x;   // 128
    double a1 = 0.0, a2 = 0.0;
    for (int k = 0; k < 128; k++) {
        double bk = (double)b[k];
        a1 += bk * (double)W[k * 128 + j];
        a2 += bk * g_W2d[k * 128 + j];
    }
    g_c1[j] = (float)a1;
    g_c2[j] = (float)a2;
}

// ---------------- CSR build ----------------
__global__ void hist_kernel(const int* __restrict__ dst) {
    int e = blockIdx.x * blockDim.x + threadIdx.x;
    if (e < N_EDGES) atomicAdd(&g_cnt[dst[e]], 1);
}

__global__ void scan1_kernel() {
    __shared__ int sh[1024];
    int tid = threadIdx.x;
    int i = blockIdx.x * 1024 + tid;
    int v = (i < N_NODES) ? g_cnt[i] : 0;
    sh[tid] = v;
    __syncthreads();
    for (int off = 1; off < 1024; off <<= 1) {
        int t = (tid >= off) ? sh[tid - off] : 0;
        __syncthreads();
        sh[tid] += t;
        __syncthreads();
    }
    if (i < N_NODES) g_rowptr[i] = sh[tid] - v;   // exclusive
    if (tid == 1023) g_blocksums[blockIdx.x] = sh[1023];
}

__global__ void scan2_kernel(int nblocks) {
    __shared__ int sh[128];
    int tid = threadIdx.x;
    int v = (tid < nblocks) ? g_blocksums[tid] : 0;
    sh[tid] = v;
    __syncthreads();
    for (int off = 1; off < 128; off <<= 1) {
        int t = (tid >= off) ? sh[tid - off] : 0;
        __syncthreads();
        sh[tid] += t;
        __syncthreads();
    }
    if (tid < nblocks) g_blocksums[tid] = sh[tid] - v;   // exclusive
}

__global__ void scan3_kernel() {
    int i = blockIdx.x * 1024 + threadIdx.x;
    if (i < N_NODES) {
        int r = g_rowptr[i] + g_blocksums[blockIdx.x];
        g_rowptr[i] = r;
        g_cursor[i] = r;
    }
}

__global__ void scatter_kernel(const int* __restrict__ src,
                               const int* __restrict__ dst,
                               const float* __restrict__ val) {
    int e = blockIdx.x * blockDim.x + threadIdx.x;
    if (e < N_EDGES) {
        int d = dst[e];
        int pos = atomicAdd(&g_cursor[d], 1);
        g_csr_src[pos] = src[e];
        g_csr_val[pos] = val[e];
    }
}

// ---------------- degree vectors: deg1 = A·1, deg2 = A·deg1 ----------------
__global__ void deg1_kernel() {
    int i = blockIdx.x * blockDim.x + threadIdx.x;
    if (i >= N_NODES) return;
    int s = g_rowptr[i], e = g_cursor[i];
    float acc = 0.f;
    for (int j = s; j < e; j++) acc += g_csr_val[j];
    g_deg1[i] = acc;
}

__global__ void deg2_kernel() {
    int i = blockIdx.x * blockDim.x + threadIdx.x;
    if (i >= N_NODES) return;
    int s = g_rowptr[i], e = g_cursor[i];
    float acc = 0.f;
    for (int j = s; j < e; j++) acc += g_csr_val[j] * g_deg1[g_csr_src[j]];
    g_deg2[i] = acc;
}

// ---------------- embedding concat ----------------
__global__ void embed_kernel(const int* __restrict__ nodef,
                             const int* __restrict__ typef,
                             const int* __restrict__ lenf,
                             const int* __restrict__ lanef,
                             const float* __restrict__ node_emb,
                             const float* __restrict__ type_emb,
                             const float* __restrict__ len_emb,
                             const float* __restrict__ lane_emb) {
    int u = blockIdx.x * blockDim.x + threadIdx.x;
    if (u >= N_NODES * 32) return;
    int n = u >> 5;
    int c = u & 31;
    float4 v;
    if (c < 4) {
        int f = lanef[n];
        v = reinterpret_cast<const float4*>(lane_emb + (size_t)f * 16)[c];
    } else if (c < 12) {
        int f = typef[n];
        v = reinterpret_cast<const float4*>(type_emb + (size_t)f * 32)[c - 4];
    } else if (c < 16) {
        int f = lenf[n];
        v = reinterpret_cast<const float4*>(len_emb + (size_t)f * 16)[c - 12];
    } else {
        int f = nodef[n];
        v = reinterpret_cast<const float4*>(node_emb + (size_t)f * 64)[c - 16];
    }
    reinterpret_cast<float4*>(g_A)[u] = v;
}

// ---------------- GEMM: FFMA2 k-pair accumulation, col-split W, 3 CTAs/SM ----------------
// (unchanged from R14; now runs ONCE with W = W^3)
#define XN_STRIDE 132
#define ROW_TILES64 ((N_NODES + 63) / 64)     // 1563
#define HALF_CTAS 222
#define SMEM_GEMM (64 * 64 * 8 + 64 * XN_STRIDE * 4)   // 66560

__device__ __forceinline__ void ffma2(ull& acc, ull a, ull b) {
    asm("fma.rn.f32x2 %0, %1, %2, %0;" : "+l"(acc) : "l"(a), "l"(b));
}

__global__ __launch_bounds__(256, 3)
void gemm_kernel(const float* __restrict__ X,
                 const float* __restrict__ W,
                 float* __restrict__ S) {
    extern __shared__ float sh[];
    ull*   wp = reinterpret_cast<ull*>(sh);          // [64 k2][64 c]
    float* xs = sh + 64 * 64 * 2;                    // 64 x XN_STRIDE
    int tid = threadIdx.x;
    int half  = (blockIdx.x >= HALF_CTAS) ? 1 : 0;
    int cbase = half * 64;

    for (int i = tid; i < 64 * 64; i += 256) {
        int k2 = i >> 6, c = i & 63;
        float w0 = W[(2 * k2) * 128 + cbase + c];
        float w1 = W[(2 * k2 + 1) * 128 + cbase + c];
        ull v;
        asm("mov.b64 %0, {%1, %2};" : "=l"(v) : "f"(w0), "f"(w1));
        wp[i] = v;
    }

    int tx = tid & 15;
    int ty = tid >> 4;

    for (int tile = blockIdx.x % HALF_CTAS; tile < ROW_TILES64; tile += HALF_CTAS) {
        int row0 = tile * 64;
        __syncthreads();
        for (int i = tid; i < 64 * 32; i += 256) {
            int r = i >> 5, c4 = i & 31;
            int gr = row0 + r;
            float4 v = make_float4(0.f, 0.f, 0.f, 0.f);
            if (gr < N_NODES)
                v = reinterpret_cast<const float4*>(X + (size_t)gr * 128)[c4];
            *reinterpret_cast<float4*>(xs + r * XN_STRIDE + 4 * c4) = v;
        }
        __syncthreads();

        ull acc[4][4];
#pragma unroll
        for (int i = 0; i < 4; i++)
#pragma unroll
            for (int j = 0; j < 4; j++) acc[i][j] = 0ull;

#pragma unroll 8
        for (int k2 = 0; k2 < 64; k2++) {
            ull w[4];
#pragma unroll
            for (int j = 0; j < 4; j++) w[j] = wp[k2 * 64 + tx + 16 * j];
            ull x[4];
#pragma unroll
            for (int i = 0; i < 4; i++)
                x[i] = *reinterpret_cast<const ull*>(xs + (ty + 16 * i) * XN_STRIDE + 2 * k2);
#pragma unroll
            for (int i = 0; i < 4; i++)
#pragma unroll
                for (int j = 0; j < 4; j++)
                    ffma2(acc[i][j], x[i], w[j]);
        }

#pragma unroll
        for (int i = 0; i < 4; i++) {
            int gr = row0 + ty + 16 * i;
            if (gr < N_NODES) {
                float* out = S + (size_t)gr * 128 + cbase + tx;
#pragma unroll
                for (int j = 0; j < 4; j++) {
                    float2 a = *reinterpret_cast<float2*>(&acc[i][j]);
                    out[16 * j] = a.x + a.y;
                }
            }
        }
    }
}

// ---------------- aggregation: plain T_out[d] = sum val_e * T_in[src_e] ----------------
__global__ void agg_plain_kernel(const float* __restrict__ S,
                                 float* __restrict__ out) {
    int warp = (blockIdx.x * blockDim.x + threadIdx.x) >> 5;
    int lane = threadIdx.x & 31;
    if (warp >= N_NODES) return;
    float4 acc = make_float4(0.f, 0.f, 0.f, 0.f);
    int s = g_rowptr[warp];
    int e = g_cursor[warp];
    for (int j = s; j < e; j++) {
        int src = __ldg(&g_csr_src[j]);
        float v = __ldg(&g_csr_val[j]);
        float4 x = reinterpret_cast<const float4*>(S + (size_t)src * 128)[lane];
        acc.x = fmaf(v, x.x, acc.x);
        acc.y = fmaf(v, x.y, acc.y);
        acc.z = fmaf(v, x.z, acc.z);
        acc.w = fmaf(v, x.w, acc.w);
    }
    reinterpret_cast<float4*>(out + (size_t)warp * 128)[lane] = acc;
}

// ---------------- final aggregation + rank-1 bias corrections ----------------
// out[d] = A·T2 [d] + deg2[d]*c2 + deg1[d]*c1 + b
__global__ void agg_final_kernel(const float* __restrict__ S,
                                 const float* __restrict__ b,
                                 float* __restrict__ out) {
    int warp = (blockIdx.x * blockDim.x + threadIdx.x) >> 5;
    int lane = threadIdx.x & 31;
    if (warp >= N_NODES) return;
    float d1 = g_deg1[warp], d2 = g_deg2[warp];
    float4 bv  = reinterpret_cast<const float4*>(b)[lane];
    float4 c1v = reinterpret_cast<const float4*>(g_c1)[lane];
    float4 c2v = reinterpret_cast<const float4*>(g_c2)[lane];
    float4 acc;
    acc.x = bv.x + d1 * c1v.x + d2 * c2v.x;
    acc.y = bv.y + d1 * c1v.y + d2 * c2v.y;
    acc.z = bv.z + d1 * c1v.z + d2 * c2v.z;
    acc.w = bv.w + d1 * c1v.w + d2 * c2v.w;
    int s = g_rowptr[warp];
    int e = g_cursor[warp];
    for (int j = s; j < e; j++) {
        int src = __ldg(&g_csr_src[j]);
        float v = __ldg(&g_csr_val[j]);
        float4 x = reinterpret_cast<const float4*>(S + (size_t)src * 128)[lane];
        acc.x = fmaf(v, x.x, acc.x);
        acc.y = fmaf(v, x.y, acc.y);
        acc.z = fmaf(v, x.z, acc.z);
        acc.w = fmaf(v, x.w, acc.w);
    }
    reinterpret_cast<float4*>(out + (size_t)warp * 128)[lane] = acc;
}

// ---------------- launch ----------------
extern "C" void kernel_launch(void* const* d_in, const int* in_sizes, int n_in,
                              void* d_out, int out_size) {
    const int*   nodef    = (const int*)d_in[0];
    const int*   typef    = (const int*)d_in[1];
    const int*   lenf     = (const int*)d_in[2];
    const int*   lanef    = (const int*)d_in[3];
    const int*   adj_src  = (const int*)d_in[4];
    const int*   adj_dst  = (const int*)d_in[5];
    const float* adj_val  = (const float*)d_in[6];
    const float* node_emb = (const float*)d_in[7];
    const float* type_emb = (const float*)d_in[8];
    const float* len_emb  = (const float*)d_in[9];
    const float* lane_emb = (const float*)d_in[10];
    const float* W        = (const float*)d_in[11];
    const float* b        = (const float*)d_in[12];
    float* out = (float*)d_out;

    float *pA, *pB, *pS, *pW3;
    int* pcnt;
    cudaGetSymbolAddress((void**)&pA, g_A);
    cudaGetSymbolAddress((void**)&pB, g_B);
    cudaGetSymbolAddress((void**)&pS, g_S);
    cudaGetSymbolAddress((void**)&pW3, g_W3);
    cudaGetSymbolAddress((void**)&pcnt, g_cnt);

    cudaFuncSetAttribute(gemm_kernel, cudaFuncAttributeMaxDynamicSharedMemorySize, SMEM_GEMM);

    const int gemm_blocks = 2 * HALF_CTAS;              // 444 persistent, 3 CTAs/SM
    const int agg_blocks  = (N_NODES * 32 + 255) / 256;
    const int nscan = (N_NODES + 1023) / 1024;          // 98

    // idx 0..4 ordered so ncu (launch index 4) captures the GEMM:
    cudaMemsetAsync(pcnt, 0, N_NODES * sizeof(int));                            // 0
    embed_kernel<<<(N_NODES * 32 + 255) / 256, 256>>>(nodef, typef, lenf, lanef,
                                                      node_emb, type_emb, len_emb, lane_emb); // 1
    w2_kernel<<<64, 256>>>(W);                                                  // 2
    w3_kernel<<<64, 256>>>(W);                                                  // 3
    gemm_kernel<<<gemm_blocks, 256, SMEM_GEMM>>>(pA, pW3, pS);                  // 4 (profiled)
    c12_kernel<<<1, 128>>>(W, b);                                               // 5
    hist_kernel<<<(N_EDGES + 255) / 256, 256>>>(adj_dst);                       // 6
    scan1_kernel<<<nscan, 1024>>>();                                            // 7
    scan2_kernel<<<1, 128>>>(nscan);                                            // 8
    scan3_kernel<<<nscan, 1024>>>();                                            // 9
    scatter_kernel<<<(N_EDGES + 255) / 256, 256>>>(adj_src, adj_dst, adj_val);  // 10
    deg1_kernel<<<(N_NODES + 255) / 256, 256>>>();                              // 11
    deg2_kernel<<<(N_NODES + 255) / 256, 256>>>();                              // 12

    // A^3 applied to Y, rank-1 bias corrections in the last pass
    agg_plain_kernel<<<agg_blocks, 256>>>(pS, pB);        // T1 = A·Y
    agg_plain_kernel<<<agg_blocks, 256>>>(pB, pA);        // T2 = A·T1
    agg_final_kernel<<<agg_blocks, 256>>>(pA, b, out);    // out = A·T2 + corrections
}

// round 16
// speedup vs baseline: 1.7566x; 1.0098x over previous
#include <cuda_runtime.h>
#include <cstdint>

#define N_NODES 100000
#define N_EDGES 640000
#define HID     128

typedef unsigned long long ull;

// ---------------- scratch (static device globals; no allocation) ----------------
__device__ float  g_A[(size_t)N_NODES * HID];   // embed out / T2
__device__ float  g_B[(size_t)N_NODES * HID];   // T1
__device__ float  g_S[(size_t)N_NODES * HID];   // Y = X * W^3
__device__ int    g_cnt[N_NODES];
__device__ int    g_rowptr[N_NODES];
__device__ int    g_cursor[N_NODES];
__device__ ull    g_csr_pack[N_EDGES];          // {val:32 | src:32} packed edges
__device__ int    g_blocksums[128];
__device__ double g_W2d[128 * 128];             // W^2 in fp64
__device__ float  g_W3[128 * 128];              // W^3 fp32 (GEMM operand)
__device__ float  g_c1[HID];                    // b^T W
__device__ float  g_c2[HID];                    // b^T W^2
__device__ float  g_deg1[N_NODES];              // A·1
__device__ float  g_deg2[N_NODES];              // A²·1

// ---------------- small matrix prep (fp64 accumulation) ----------------
__global__ void w2_kernel(const float* __restrict__ W) {
    int i = blockIdx.x * blockDim.x + threadIdx.x;   // 16384
    int r = i >> 7, c = i & 127;
    double acc = 0.0;
    for (int k = 0; k < 128; k++)
        acc += (double)W[r * 128 + k] * (double)W[k * 128 + c];
    g_W2d[i] = acc;
}

__global__ void w3_kernel(const float* __restrict__ W) {
    int i = blockIdx.x * blockDim.x + threadIdx.x;
    int r = i >> 7, c = i & 127;
    double acc = 0.0;
    for (int k = 0; k < 128; k++)
        acc += g_W2d[r * 128 + k] * (double)W[k * 128 + c];
    g_W3[i] = (float)acc;
}

__global__ void c12_kernel(const float* __restrict__ W, const float* __restrict__ b) {
    int j = threadIdx.x;   // 128
    double a1 = 0.0, a2 = 0.0;
    for (int k = 0; k < 128; k++) {
        double bk = (double)b[k];
        a1 += bk * (double)W[k * 128 + j];
        a2 += bk * g_W2d[k * 128 + j];
    }
    g_c1[j] = (float)a1;
    g_c2[j] = (float)a2;
}

// ---------------- CSR build ----------------
__global__ void hist_kernel(const int* __restrict__ dst) {
    int e = blockIdx.x * blockDim.x + threadIdx.x;
    if (e < N_EDGES) atomicAdd(&g_cnt[dst[e]], 1);
}

__global__ void scan1_kernel() {
    __shared__ int sh[1024];
    int tid = threadIdx.x;
    int i = blockIdx.x * 1024 + tid;
    int v = (i < N_NODES) ? g_cnt[i] : 0;
    sh[tid] = v;
    __syncthreads();
    for (int off = 1; off < 1024; off <<= 1) {
        int t = (tid >= off) ? sh[tid - off] : 0;
        __syncthreads();
        sh[tid] += t;
        __syncthreads();
    }
    if (i < N_NODES) g_rowptr[i] = sh[tid] - v;   // exclusive
    if (tid == 1023) g_blocksums[blockIdx.x] = sh[1023];
}

__global__ void scan2_kernel(int nblocks) {
    __shared__ int sh[128];
    int tid = threadIdx.x;
    int v = (tid < nblocks) ? g_blocksums[tid] : 0;
    sh[tid] = v;
    __syncthreads();
    for (int off = 1; off < 128; off <<= 1) {
        int t = (tid >= off) ? sh[tid - off] : 0;
        __syncthreads();
        sh[tid] += t;
        __syncthreads();
    }
    if (tid < nblocks) g_blocksums[tid] = sh[tid] - v;   // exclusive
}

__global__ void scan3_kernel() {
    int i = blockIdx.x * 1024 + threadIdx.x;
    if (i < N_NODES) {
        int r = g_rowptr[i] + g_blocksums[blockIdx.x];
        g_rowptr[i] = r;
        g_cursor[i] = r;
    }
}

__global__ void scatter_kernel(const int* __restrict__ src,
                               const int* __restrict__ dst,
                               const float* __restrict__ val) {
    int e = blockIdx.x * blockDim.x + threadIdx.x;
    if (e < N_EDGES) {
        int d = dst[e];
        int pos = atomicAdd(&g_cursor[d], 1);
        ull p = (ull)(unsigned)src[e] | ((ull)__float_as_uint(val[e]) << 32);
        g_csr_pack[pos] = p;
    }
}

// ---------------- degree vectors: deg1 = A·1, deg2 = A·deg1 ----------------
__global__ void deg1_kernel() {
    int i = blockIdx.x * blockDim.x + threadIdx.x;
    if (i >= N_NODES) return;
    int s = g_rowptr[i], e = g_cursor[i];
    float acc = 0.f;
    for (int j = s; j < e; j++)
        acc += __uint_as_float((unsigned)(g_csr_pack[j] >> 32));
    g_deg1[i] = acc;
}

__global__ void deg2_kernel() {
    int i = blockIdx.x * blockDim.x + threadIdx.x;
    if (i >= N_NODES) return;
    int s = g_rowptr[i], e = g_cursor[i];
    float acc = 0.f;
    for (int j = s; j < e; j++) {
        ull p = g_csr_pack[j];
        acc += __uint_as_float((unsigned)(p >> 32)) * g_deg1[(unsigned)(p & 0xffffffffu)];
    }
    g_deg2[i] = acc;
}

// ---------------- embedding concat ----------------
__global__ void embed_kernel(const int* __restrict__ nodef,
                             const int* __restrict__ typef,
                             const int* __restrict__ lenf,
                             const int* __restrict__ lanef,
                             const float* __restrict__ node_emb,
                             const float* __restrict__ type_emb,
                             const float* __restrict__ len_emb,
                             const float* __restrict__ lane_emb) {
    int u = blockIdx.x * blockDim.x + threadIdx.x;
    if (u >= N_NODES * 32) return;
    int n = u >> 5;
    int c = u & 31;
    float4 v;
    if (c < 4) {
        int f = lanef[n];
        v = reinterpret_cast<const float4*>(lane_emb + (size_t)f * 16)[c];
    } else if (c < 12) {
        int f = typef[n];
        v = reinterpret_cast<const float4*>(type_emb + (size_t)f * 32)[c - 4];
    } else if (c < 16) {
        int f = lenf[n];
        v = reinterpret_cast<const float4*>(len_emb + (size_t)f * 16)[c - 12];
    } else {
        int f = nodef[n];
        v = reinterpret_cast<const float4*>(node_emb + (size_t)f * 64)[c - 16];
    }
    reinterpret_cast<float4*>(g_A)[u] = v;
}

// ---------------- GEMM: FFMA2 k-pair accumulation, col-split W, 3 CTAs/SM ----------------
// (unchanged from R14/R15; runs ONCE with W = W^3)
#define XN_STRIDE 132
#define ROW_TILES64 ((N_NODES + 63) / 64)     // 1563
#define HALF_CTAS 222
#define SMEM_GEMM (64 * 64 * 8 + 64 * XN_STRIDE * 4)   // 66560

__device__ __forceinline__ void ffma2(ull& acc, ull a, ull b) {
    asm("fma.rn.f32x2 %0, %1, %2, %0;" : "+l"(acc) : "l"(a), "l"(b));
}

__global__ __launch_bounds__(256, 3)
void gemm_kernel(const float* __restrict__ X,
                 const float* __restrict__ W,
                 float* __restrict__ S) {
    extern __shared__ float sh[];
    ull*   wp = reinterpret_cast<ull*>(sh);          // [64 k2][64 c]
    float* xs = sh + 64 * 64 * 2;                    // 64 x XN_STRIDE
    int tid = threadIdx.x;
    int half  = (blockIdx.x >= HALF_CTAS) ? 1 : 0;
    int cbase = half * 64;

    for (int i = tid; i < 64 * 64; i += 256) {
        int k2 = i >> 6, c = i & 63;
        float w0 = W[(2 * k2) * 128 + cbase + c];
        float w1 = W[(2 * k2 + 1) * 128 + cbase + c];
        ull v;
        asm("mov.b64 %0, {%1, %2};" : "=l"(v) : "f"(w0), "f"(w1));
        wp[i] = v;
    }

    int tx = tid & 15;
    int ty = tid >> 4;

    for (int tile = blockIdx.x % HALF_CTAS; tile < ROW_TILES64; tile += HALF_CTAS) {
        int row0 = tile * 64;
        __syncthreads();
        for (int i = tid; i < 64 * 32; i += 256) {
            int r = i >> 5, c4 = i & 31;
            int gr = row0 + r;
            float4 v = make_float4(0.f, 0.f, 0.f, 0.f);
            if (gr < N_NODES)
                v = reinterpret_cast<const float4*>(X + (size_t)gr * 128)[c4];
            *reinterpret_cast<float4*>(xs + r * XN_STRIDE + 4 * c4) = v;
        }
        __syncthreads();

        ull acc[4][4];
#pragma unroll
        for (int i = 0; i < 4; i++)
#pragma unroll
            for (int j = 0; j < 4; j++) acc[i][j] = 0ull;

#pragma unroll 8
        for (int k2 = 0; k2 < 64; k2++) {
            ull w[4];
#pragma unroll
            for (int j = 0; j < 4; j++) w[j] = wp[k2 * 64 + tx + 16 * j];
            ull x[4];
#pragma unroll
            for (int i = 0; i < 4; i++)
                x[i] = *reinterpret_cast<const ull*>(xs + (ty + 16 * i) * XN_STRIDE + 2 * k2);
#pragma unroll
            for (int i = 0; i < 4; i++)
#pragma unroll
                for (int j = 0; j < 4; j++)
                    ffma2(acc[i][j], x[i], w[j]);
        }

#pragma unroll
        for (int i = 0; i < 4; i++) {
            int gr = row0 + ty + 16 * i;
            if (gr < N_NODES) {
                float* out = S + (size_t)gr * 128 + cbase + tx;
#pragma unroll
                for (int j = 0; j < 4; j++) {
                    float2 a = *reinterpret_cast<float2*>(&acc[i][j]);
                    out[16 * j] = a.x + a.y;
                }
            }
        }
    }
}

// ---------------- aggregation (MLP-4 unrolled, packed edges) ----------------
__device__ __forceinline__ void agg_body(const float* __restrict__ S,
                                         float* __restrict__ out,
                                         int node, int lane, float4 acc) {
    int s = g_rowptr[node];
    int e = g_cursor[node];
    int j = s;
    for (; j + 4 <= e; j += 4) {
        ull p0 = __ldg(&g_csr_pack[j]);
        ull p1 = __ldg(&g_csr_pack[j + 1]);
        ull p2 = __ldg(&g_csr_pack[j + 2]);
        ull p3 = __ldg(&g_csr_pack[j + 3]);
        const float4* r0 = reinterpret_cast<const float4*>(S + (size_t)(unsigned)(p0 & 0xffffffffu) * 128);
        const float4* r1 = reinterpret_cast<const float4*>(S + (size_t)(unsigned)(p1 & 0xffffffffu) * 128);
        const float4* r2 = reinterpret_cast<const float4*>(S + (size_t)(unsigned)(p2 & 0xffffffffu) * 128);
        const float4* r3 = reinterpret_cast<const float4*>(S + (size_t)(unsigned)(p3 & 0xffffffffu) * 128);
        float4 x0 = __ldg(&r0[lane]);
        float4 x1 = __ldg(&r1[lane]);
        float4 x2 = __ldg(&r2[lane]);
        float4 x3 = __ldg(&r3[lane]);
        float v0 = __uint_as_float((unsigned)(p0 >> 32));
        float v1 = __uint_as_float((unsigned)(p1 >> 32));
        float v2 = __uint_as_float((unsigned)(p2 >> 32));
        float v3 = __uint_as_float((unsigned)(p3 >> 32));
        acc.x = fmaf(v0, x0.x, acc.x); acc.y = fmaf(v0, x0.y, acc.y);
        acc.z = fmaf(v0, x0.z, acc.z); acc.w = fmaf(v0, x0.w, acc.w);
        acc.x = fmaf(v1, x1.x, acc.x); acc.y = fmaf(v1, x1.y, acc.y);
        acc.z = fmaf(v1, x1.z, acc.z); acc.w = fmaf(v1, x1.w, acc.w);
        acc.x = fmaf(v2, x2.x, acc.x); acc.y = fmaf(v2, x2.y, acc.y);
        acc.z = fmaf(v2, x2.z, acc.z); acc.w = fmaf(v2, x2.w, acc.w);
        acc.x = fmaf(v3, x3.x, acc.x); acc.y = fmaf(v3, x3.y, acc.y);
        acc.z = fmaf(v3, x3.z, acc.z); acc.w = fmaf(v3, x3.w, acc.w);
    }
    for (; j < e; j++) {
        ull p = __ldg(&g_csr_pack[j]);
        float v = __uint_as_float((unsigned)(p >> 32));
        const float4* r = reinterpret_cast<const float4*>(S + (size_t)(unsigned)(p & 0xffffffffu) * 128);
        float4 x = __ldg(&r[lane]);
        acc.x = fmaf(v, x.x, acc.x); acc.y = fmaf(v, x.y, acc.y);
        acc.z = fmaf(v, x.z, acc.z); acc.w = fmaf(v, x.w, acc.w);
    }
    reinterpret_cast<float4*>(out + (size_t)node * 128)[lane] = acc;
}

__global__ void agg_plain_kernel(const float* __restrict__ S,
                                 float* __restrict__ out) {
    int warp = (blockIdx.x * blockDim.x + threadIdx.x) >> 5;
    int lane = threadIdx.x & 31;
    if (warp >= N_NODES) return;
    agg_body(S, out, warp, lane, make_float4(0.f, 0.f, 0.f, 0.f));
}

// out[d] = A·T2 [d] + deg2[d]*c2 + deg1[d]*c1 + b
__global__ void agg_final_kernel(const float* __restrict__ S,
                                 const float* __restrict__ b,
                                 float* __restrict__ out) {
    int warp = (blockIdx.x * blockDim.x + threadIdx.x) >> 5;
    int lane = threadIdx.x & 31;
    if (warp >= N_NODES) return;
    float d1 = g_deg1[warp], d2 = g_deg2[warp];
    float4 bv  = reinterpret_cast<const float4*>(b)[lane];
    float4 c1v = reinterpret_cast<const float4*>(g_c1)[lane];
    float4 c2v = reinterpret_cast<const float4*>(g_c2)[lane];
    float4 acc;
    acc.x = bv.x + d1 * c1v.x + d2 * c2v.x;
    acc.y = bv.y + d1 * c1v.y + d2 * c2v.y;
    acc.z = bv.z + d1 * c1v.z + d2 * c2v.z;
    acc.w = bv.w + d1 * c1v.w + d2 * c2v.w;
    agg_body(S, out, warp, lane, acc);
}

// ---------------- launch ----------------
extern "C" void kernel_launch(void* const* d_in, const int* in_sizes, int n_in,
                              void* d_out, int out_size) {
    const int*   nodef    = (const int*)d_in[0];
    const int*   typef    = (const int*)d_in[1];
    const int*   lenf     = (const int*)d_in[2];
    const int*   lanef    = (const int*)d_in[3];
    const int*   adj_src  = (const int*)d_in[4];
    const int*   adj_dst  = (const int*)d_in[5];
    const float* adj_val  = (const float*)d_in[6];
    const float* node_emb = (const float*)d_in[7];
    const float* type_emb = (const float*)d_in[8];
    const float* len_emb  = (const float*)d_in[9];
    const float* lane_emb = (const float*)d_in[10];
    const float* W        = (const float*)d_in[11];
    const float* b        = (const float*)d_in[12];
    float* out = (float*)d_out;

    float *pA, *pB, *pS, *pW3;
    int* pcnt;
    cudaGetSymbolAddress((void**)&pA, g_A);
    cudaGetSymbolAddress((void**)&pB, g_B);
    cudaGetSymbolAddress((void**)&pS, g_S);
    cudaGetSymbolAddress((void**)&pW3, g_W3);
    cudaGetSymbolAddress((void**)&pcnt, g_cnt);

    cudaFuncSetAttribute(gemm_kernel, cudaFuncAttributeMaxDynamicSharedMemorySize, SMEM_GEMM);

    const int gemm_blocks = 2 * HALF_CTAS;              // 444 persistent, 3 CTAs/SM
    const int agg_blocks  = (N_NODES * 32 + 255) / 256;
    const int nscan = (N_NODES + 1023) / 1024;          // 98

    // idx 0..4 ordered so ncu (launch index 4) captures the GEMM:
    cudaMemsetAsync(pcnt, 0, N_NODES * sizeof(int));                            // 0
    embed_kernel<<<(N_NODES * 32 + 255) / 256, 256>>>(nodef, typef, lenf, lanef,
                                                      node_emb, type_emb, len_emb, lane_emb); // 1
    w2_kernel<<<64, 256>>>(W);                                                  // 2
    w3_kernel<<<64, 256>>>(W);                                                  // 3
    gemm_kernel<<<gemm_blocks, 256, SMEM_GEMM>>>(pA, pW3, pS);                  // 4 (profiled)
    c12_kernel<<<1, 128>>>(W, b);                                               // 5
    hist_kernel<<<(N_EDGES + 255) / 256, 256>>>(adj_dst);                       // 6
    scan1_kernel<<<nscan, 1024>>>();                                            // 7
    scan2_kernel<<<1, 128>>>(nscan);                                            // 8
    scan3_kernel<<<nscan, 1024>>>();                                            // 9
    scatter_kernel<<<(N_EDGES + 255) / 256, 256>>>(adj_src, adj_dst, adj_val);  // 10
    deg1_kernel<<<(N_NODES + 255) / 256, 256>>>();                              // 11
    deg2_kernel<<<(N_NODES + 255) / 256, 256>>>();                              // 12

    // A^3 applied to Y, rank-1 bias corrections in the last pass
    agg_plain_kernel<<<agg_blocks, 256>>>(pS, pB);        // T1 = A·Y
    agg_plain_kernel<<<agg_blocks, 256>>>(pB, pA);        // T2 = A·T1
    agg_final_kernel<<<agg_blocks, 256>>>(pA, b, out);    // out = A·T2 + corrections
}